// round 11
// baseline (speedup 1.0000x reference)
#include <cuda_runtime.h>

// SimpleLSTM fused persistent kernel (fp32).
// B=64, T=2048, I=H=512. 256 CTAs x 128 threads; CTA c owns hidden columns
// {2c, 2c+1} (8 gate rows i0,i1,f0,f1,g0,g1,o0,o1). Weight slices live in
// smem (XOR-swizzled, bank-conflict-free) for the whole kernel. h is
// exchanged through a global double buffer + one grid barrier per timestep.

#define BB 64
#define TT 2048
#define II 512
#define HH 512
#define NCTA 256
#define NTHR 128

__device__ __align__(16) float g_hbuf[2][BB * HH]; // [buf][b*HH + col]
__device__ unsigned g_count; // cumulative barrier arrivals (never reset; wrap-safe)
__device__ unsigned g_phase; // cumulative barrier releases

__device__ __forceinline__ float tanh_fast(float x) {
    float y;
    asm("tanh.approx.f32 %0, %1;" : "=f"(y) : "f"(x));
    return y;
}
__device__ __forceinline__ float sig_fast(float x) {
    return fmaf(0.5f, tanh_fast(0.5f * x), 0.5f);
}

#define EL(v, e) ((e) == 0 ? (v).x : ((e) == 1 ? (v).y : ((e) == 2 ? (v).z : (v).w)))

// One K=512 matvec phase. Thread accumulates 8 rows x 4 batches over its
// 1/8 k-slice (16 quads, interleaved by ks for coalescing).
// Weight smem layout: logical float4 slot L = k*2 + half stored at
// phys = L ^ ((k>>2)&7)  -> the 8 ks-lanes (k stride 4) land on 8 distinct
// bank-octets: conflict-free LDS.128.
template <bool CG>
__device__ __forceinline__ void mvphase(
    float* acc,
    const float* p0, const float* p1, const float* p2, const float* p3,
    const float4* __restrict__ W4, int ks)
{
#pragma unroll 2
    for (int q = 0; q < 16; q++) {
        int k0 = (q * 8 + ks) * 4;
        float4 a0, a1, a2, a3;
        if (CG) {
            a0 = __ldcg((const float4*)(p0 + k0));
            a1 = __ldcg((const float4*)(p1 + k0));
            a2 = __ldcg((const float4*)(p2 + k0));
            a3 = __ldcg((const float4*)(p3 + k0));
        } else {
            a0 = *(const float4*)(p0 + k0);
            a1 = *(const float4*)(p1 + k0);
            a2 = *(const float4*)(p2 + k0);
            a3 = *(const float4*)(p3 + k0);
        }
#pragma unroll
        for (int e = 0; e < 4; e++) {
            int k = k0 + e;
            int sw = (k >> 2) & 7;
            float4 w0 = W4[(k * 2) ^ sw];     // rows 0..3 at k
            float4 w1 = W4[(k * 2 + 1) ^ sw]; // rows 4..7 at k
            float b0 = EL(a0, e), b1 = EL(a1, e), b2 = EL(a2, e), b3 = EL(a3, e);
#define R8(ai, wv)                                   \
    acc[(ai)*4 + 0] = fmaf((wv), b0, acc[(ai)*4 + 0]); \
    acc[(ai)*4 + 1] = fmaf((wv), b1, acc[(ai)*4 + 1]); \
    acc[(ai)*4 + 2] = fmaf((wv), b2, acc[(ai)*4 + 2]); \
    acc[(ai)*4 + 3] = fmaf((wv), b3, acc[(ai)*4 + 3]);
            R8(0, w0.x) R8(1, w0.y) R8(2, w0.z) R8(3, w0.w)
            R8(4, w1.x) R8(5, w1.y) R8(6, w1.z) R8(7, w1.w)
#undef R8
        }
    }
}

__global__ void __launch_bounds__(NTHR, 2) lstm_persistent(
    const float* __restrict__ x,   // [B][T][I]
    const float* __restrict__ Wx,  // [4H][I]
    const float* __restrict__ bx,  // [4H]
    const float* __restrict__ Wh,  // [4H][H]
    const float* __restrict__ bh,  // [4H]
    float* __restrict__ out,       // [B][T][H] (+ optional h_n, c_n)
    int write_hn, int write_cn)
{
    __shared__ float4 W4x[1024]; // 512 k x 2 halves, swizzled
    __shared__ float4 W4h[1024];
    __shared__ float  s_bias[8];
    __shared__ unsigned s_base;

    const int tid = threadIdx.x;
    const int bg  = tid >> 3;   // 0..15 -> batches bg*4 .. bg*4+3
    const int ks  = tid & 7;    // k-split lane within 8
    const int j0  = blockIdx.x * 2;

    // row for local row index r = gate*2 + ci  ->  gate*HH + j0 + ci
#define GROW(r) ((size_t)(((r) >> 1) * HH + j0 + ((r) & 1)))

    // Stage weight slices into smem (swizzled).
    for (int idx = tid; idx < 1024; idx += NTHR) {
        int k = idx >> 1, hh = idx & 1;
        int sw = (k >> 2) & 7;
        int r0 = hh * 4;
        float4 vx, vh;
        vx.x = Wx[GROW(r0 + 0) * II + k];
        vx.y = Wx[GROW(r0 + 1) * II + k];
        vx.z = Wx[GROW(r0 + 2) * II + k];
        vx.w = Wx[GROW(r0 + 3) * II + k];
        vh.x = Wh[GROW(r0 + 0) * HH + k];
        vh.y = Wh[GROW(r0 + 1) * HH + k];
        vh.z = Wh[GROW(r0 + 2) * HH + k];
        vh.w = Wh[GROW(r0 + 3) * HH + k];
        W4x[idx ^ sw] = vx;
        W4h[idx ^ sw] = vh;
    }
    if (tid < 8) {
        size_t row = GROW(tid);
        s_bias[tid] = bx[row] + bh[row];
    }
    if (tid == 0) s_base = *(volatile unsigned*)&g_phase; // stable pre-first-barrier
    __syncthreads();

    const unsigned base = s_base;

    // Per-thread activation row offsets (batches bg*4 + 0..3).
    const size_t xo0 = (size_t)(bg * 4 + 0) * TT * II;
    const size_t xo1 = (size_t)(bg * 4 + 1) * TT * II;
    const size_t xo2 = (size_t)(bg * 4 + 2) * TT * II;
    const size_t xo3 = (size_t)(bg * 4 + 3) * TT * II;
    const int ho0 = (bg * 4 + 0) * HH;
    const int ho1 = (bg * 4 + 1) * HH;
    const int ho2 = (bg * 4 + 2) * HH;
    const int ho3 = (bg * 4 + 3) * HH;

    // This lane's output element: (col = j0 + ks>>2, batch = bg*4 + (ks&3))
    const int myb   = bg * 4 + (ks & 3);
    const int mycol = j0 + (ks >> 2);

    float cst[8];
#pragma unroll
    for (int cc = 0; cc < 8; cc++) cst[cc] = 0.0f;

    float myh = 0.0f, myc = 0.0f;

    for (int t = 0; t < TT; t++) {
        float acc[32];
#pragma unroll
        for (int v = 0; v < 32; v++) acc[v] = 0.0f;

        // x projection for timestep t
        const float* xt = x + (size_t)t * II;
        mvphase<false>(acc, xt + xo0, xt + xo1, xt + xo2, xt + xo3, W4x, ks);

        // recurrent projection (h == 0 at t == 0)
        if (t) {
            const float* hb = g_hbuf[t & 1];
            mvphase<true>(acc, hb + ho0, hb + ho1, hb + ho2, hb + ho3, W4h, ks);
        }

        // Reduce the 8-way k-split (contiguous 8-lane groups within the warp).
#pragma unroll
        for (int v = 0; v < 32; v++) {
            float s = acc[v];
            s += __shfl_xor_sync(0xffffffffu, s, 1);
            s += __shfl_xor_sync(0xffffffffu, s, 2);
            s += __shfl_xor_sync(0xffffffffu, s, 4);
            acc[v] = s;
        }

        // Pointwise: every lane redundantly updates all 8 (ci,bi) states of
        // its bg (keeps indexing compile-time; lanes in an 8-group stay
        // consistent), writes only its own element.
#pragma unroll
        for (int cc = 0; cc < 8; cc++) {
            const int ci = cc >> 2, bi = cc & 3;
            float si = acc[(0 + ci) * 4 + bi] + s_bias[0 + ci];
            float sf = acc[(2 + ci) * 4 + bi] + s_bias[2 + ci];
            float sg = acc[(4 + ci) * 4 + bi] + s_bias[4 + ci];
            float so = acc[(6 + ci) * 4 + bi] + s_bias[6 + ci];
            float gi = sig_fast(si);
            float gf = sig_fast(sf);
            float gg = tanh_fast(sg);
            float go = sig_fast(so);
            float c  = fmaf(gf, cst[cc], gi * gg);
            cst[cc]  = c;
            float h  = go * tanh_fast(c);
            if (cc == ks) { myh = h; myc = c; }
        }

        out[(size_t)(myb * TT + t) * HH + mycol] = myh;
        g_hbuf[(t + 1) & 1][myb * HH + mycol]    = myh;

        if (t < TT - 1) {
            // Grid barrier: cumulative-count, wrap-safe, self-consistent
            // across graph replays (counters are monotone; base read at entry).
            __syncthreads();
            if (tid == 0) {
                __threadfence();
                unsigned a = atomicAdd(&g_count, 1u) + 1u;
                if (a % NCTA == 0u) {
                    atomicAdd(&g_phase, 1u);
                } else {
                    unsigned tgt = base + (unsigned)(t + 1);
                    while ((int)(*(volatile unsigned*)&g_phase - tgt) < 0)
                        __nanosleep(64);
                }
                __threadfence();
            }
            __syncthreads();
        }
    }

    // Tail: h_n, c_n appended after output if the harness buffer includes them.
    const size_t TAIL = (size_t)BB * TT * HH;
    if (write_hn) out[TAIL + (size_t)myb * HH + mycol] = myh;
    if (write_cn) out[TAIL + (size_t)BB * HH + (size_t)myb * HH + mycol] = myc;
#undef GROW
}

extern "C" void kernel_launch(void* const* d_in, const int* in_sizes, int n_in,
                              void* d_out, int out_size) {
    const float* x  = (const float*)d_in[0];
    const float* Wx = (const float*)d_in[1];
    const float* bx = (const float*)d_in[2];
    const float* Wh = (const float*)d_in[3];
    const float* bh = (const float*)d_in[4];

    // Maximize smem carveout so 2 CTAs/SM (2 x 32.8 KB) are guaranteed
    // co-resident — required for the grid barrier. Idempotent, capture-safe.
    cudaFuncSetAttribute(lstm_persistent,
                         cudaFuncAttributePreferredSharedMemoryCarveout, 100);

    const long long TAIL = (long long)BB * TT * HH;
    int whn = ((long long)out_size >= TAIL + (long long)BB * HH) ? 1 : 0;
    int wcn = ((long long)out_size >= TAIL + 2LL * BB * HH) ? 1 : 0;

    lstm_persistent<<<NCTA, NTHR>>>(x, Wx, bx, Wh, bh, (float*)d_out, whn, wcn);
}

// round 12
// speedup vs baseline: 1.0273x; 1.0273x over previous
#include <cuda_runtime.h>

// SimpleLSTM fused persistent kernel, v2 (packed f32x2 FMA).
// B=64, T=2048, I=H=512. 128 CTAs x 256 threads; CTA owns 4 hidden columns
// (16 gate rows). Weights staged in smem once (XOR-swizzled). h exchanged via
// global double buffer + one grid barrier per step; x-projection of t+1 is
// computed before the barrier to hide barrier latency and CTA skew.
//
// Lane map (lane = tid&31): rh = lane>>4 (column-pair), bgl = (lane>>3)&1,
// ks = lane&7 (k-split). warp = tid>>5 -> batch group bg = warp*2+bgl,
// batches bg*4..bg*4+3. Thread accumulates 8 gate rows x 4 batches as
// 16 packed f32x2 pairs (row pairs = (col0,col1) of one gate).

#define BB 64
#define TT 2048
#define II 512
#define HH 512
#define NCTA 128
#define NTHR 256

__device__ __align__(16) float g_hbuf[2][BB * HH]; // [buf][b*HH + col]
__device__ unsigned g_count; // cumulative barrier arrivals (monotone)
__device__ unsigned g_phase; // cumulative barrier releases (monotone)

__device__ __forceinline__ float tanh_fast(float x) {
    float y;
    asm("tanh.approx.f32 %0, %1;" : "=f"(y) : "f"(x));
    return y;
}
__device__ __forceinline__ float sig_fast(float x) {
    return fmaf(0.5f, tanh_fast(0.5f * x), 0.5f);
}

// Packed dual-fp32 FMA (Blackwell f32x2 pipe).
__device__ __forceinline__ unsigned long long fma2(
    unsigned long long a, unsigned long long b, unsigned long long c) {
    unsigned long long d;
    asm("fma.rn.f32x2 %0, %1, %2, %3;" : "=l"(d) : "l"(a), "l"(b), "l"(c));
    return d;
}
__device__ __forceinline__ unsigned long long pack2(float lo, float hi) {
    unsigned long long r;
    asm("mov.b64 %0, {%1, %2};" : "=l"(r) : "f"(lo), "f"(hi));
    return r;
}
__device__ __forceinline__ unsigned long long dup2(float v) {
    unsigned long long r;
    asm("mov.b64 %0, {%1, %2};" : "=l"(r) : "f"(v), "f"(v));
    return r;
}
__device__ __forceinline__ void unpack2(unsigned long long p, float& lo, float& hi) {
    asm("mov.b64 {%0, %1}, %2;" : "=f"(lo), "=f"(hi) : "l"(p));
}

#define EL(v, e) ((e) == 0 ? (v).x : ((e) == 1 ? (v).y : ((e) == 2 ? (v).z : (v).w)))

// One K=512 matvec phase. pk[16] = packed (col0,col1) accumulators for
// gates 0..3 x batches 0..3. Weight smem: slot = k*4 + rh*2 + half, stored
// at phys = slot ^ ((k>>2)&7); slot content = float4 of 4 row-weights whose
// (x,y)/(z,w) pairs are the packed f32x2 operands (read as ulonglong2 -> no
// packing movs for weights). Activation scalars are duplicated via mov.b64.
template <bool CG>
__device__ __forceinline__ void mvphase(
    unsigned long long* pk,
    const float* p0, const float* p1, const float* p2, const float* p3,
    const ulonglong2* __restrict__ W, int ks, int subbase)
{
#pragma unroll 2
    for (int q = 0; q < 16; q++) {
        int k0 = (q * 8 + ks) * 4;
        float4 a0, a1, a2, a3;
        if (CG) {
            a0 = __ldcg((const float4*)(p0 + k0));
            a1 = __ldcg((const float4*)(p1 + k0));
            a2 = __ldcg((const float4*)(p2 + k0));
            a3 = __ldcg((const float4*)(p3 + k0));
        } else {
            a0 = *(const float4*)(p0 + k0);
            a1 = *(const float4*)(p1 + k0);
            a2 = *(const float4*)(p2 + k0);
            a3 = *(const float4*)(p3 + k0);
        }
#pragma unroll
        for (int e = 0; e < 4; e++) {
            int k = k0 + e;
            int sw = (k >> 2) & 7; // == ks for this thread
            int sbase = k * 4 + subbase;
            ulonglong2 w0 = W[(sbase + 0) ^ sw]; // gates 0,1 (col-pairs)
            ulonglong2 w1 = W[(sbase + 1) ^ sw]; // gates 2,3
            unsigned long long d0 = dup2(EL(a0, e));
            unsigned long long d1 = dup2(EL(a1, e));
            unsigned long long d2 = dup2(EL(a2, e));
            unsigned long long d3 = dup2(EL(a3, e));
            pk[0]  = fma2(w0.x, d0, pk[0]);
            pk[1]  = fma2(w0.x, d1, pk[1]);
            pk[2]  = fma2(w0.x, d2, pk[2]);
            pk[3]  = fma2(w0.x, d3, pk[3]);
            pk[4]  = fma2(w0.y, d0, pk[4]);
            pk[5]  = fma2(w0.y, d1, pk[5]);
            pk[6]  = fma2(w0.y, d2, pk[6]);
            pk[7]  = fma2(w0.y, d3, pk[7]);
            pk[8]  = fma2(w1.x, d0, pk[8]);
            pk[9]  = fma2(w1.x, d1, pk[9]);
            pk[10] = fma2(w1.x, d2, pk[10]);
            pk[11] = fma2(w1.x, d3, pk[11]);
            pk[12] = fma2(w1.y, d0, pk[12]);
            pk[13] = fma2(w1.y, d1, pk[13]);
            pk[14] = fma2(w1.y, d2, pk[14]);
            pk[15] = fma2(w1.y, d3, pk[15]);
        }
    }
}

__global__ void __launch_bounds__(NTHR, 1) lstm_persistent(
    const float* __restrict__ x,   // [B][T][I]
    const float* __restrict__ Wx,  // [4H][I]
    const float* __restrict__ bx,  // [4H]
    const float* __restrict__ Wh,  // [4H][H]
    const float* __restrict__ bh,  // [4H]
    float* __restrict__ out,       // [B][T][H] (+ optional h_n, c_n)
    int write_hn, int write_cn)
{
    extern __shared__ __align__(16) unsigned char smem_raw[];
    float4* W4x_st = (float4*)(smem_raw);
    float4* W4h_st = (float4*)(smem_raw + 32768);
    const ulonglong2* W4x = (const ulonglong2*)(smem_raw);
    const ulonglong2* W4h = (const ulonglong2*)(smem_raw + 32768);
    float* s_bias = (float*)(smem_raw + 65536);          // 16 floats
    unsigned* s_basep = (unsigned*)(smem_raw + 65536 + 64);

    const int tid  = threadIdx.x;
    const int warp = tid >> 5;
    const int lane = tid & 31;
    const int rh   = lane >> 4;        // column-pair half (rows rh*8..rh*8+7)
    const int bgl  = (lane >> 3) & 1;
    const int ks   = lane & 7;         // k-split lane
    const int bg   = warp * 2 + bgl;   // batch group: batches bg*4..+3
    const int ci   = ks >> 2;          // this lane's column within pair
    const int bi   = ks & 3;           // this lane's batch within group
    const int j0   = blockIdx.x * 4;
    const int subbase = rh * 2;

    // ---- Stage weight slices (16 rows x 512 k, both matrices) ----
    // slot idx = k*4 + (rrh*2 + half); float4 = rows (half*4 + 0..3) of
    // block rrh: row m -> gate = half*2 + (m>>1), col = j0 + rrh*2 + (m&1).
    for (int idx = tid; idx < 2048; idx += NTHR) {
        int k = idx >> 2, sub = idx & 3;
        int rrh = sub >> 1, half = sub & 1;
        int sw = (k >> 2) & 7;
        int phys = idx ^ sw;
        int colb = j0 + rrh * 2;
#define GR(m) ((size_t)(half * 2 + ((m) >> 1)) * HH + colb + ((m) & 1))
        float4 vx, vh;
        vx.x = Wx[GR(0) * II + k];
        vx.y = Wx[GR(1) * II + k];
        vx.z = Wx[GR(2) * II + k];
        vx.w = Wx[GR(3) * II + k];
        vh.x = Wh[GR(0) * HH + k];
        vh.y = Wh[GR(1) * HH + k];
        vh.z = Wh[GR(2) * HH + k];
        vh.w = Wh[GR(3) * HH + k];
#undef GR
        W4x_st[phys] = vx;
        W4h_st[phys] = vh;
    }
    if (tid < 16) {
        int rrh = tid >> 3, g = (tid >> 1) & 3, cc = tid & 1;
        size_t row = (size_t)g * HH + j0 + rrh * 2 + cc;
        s_bias[tid] = bx[row] + bh[row];
    }
    if (tid == 0) *s_basep = *(volatile unsigned*)&g_phase;
    __syncthreads();

    const unsigned base = *s_basep;

    unsigned long long bp[4];
#pragma unroll
    for (int g = 0; g < 4; g++)
        bp[g] = pack2(s_bias[rh * 8 + g * 2 + 0], s_bias[rh * 8 + g * 2 + 1]);

    // Activation pointers / offsets for batches bg*4 + 0..3.
    const float* px0 = x + (size_t)(bg * 4 + 0) * TT * II;
    const float* px1 = x + (size_t)(bg * 4 + 1) * TT * II;
    const float* px2 = x + (size_t)(bg * 4 + 2) * TT * II;
    const float* px3 = x + (size_t)(bg * 4 + 3) * TT * II;
    const int ho0 = (bg * 4 + 0) * HH;
    const int ho1 = (bg * 4 + 1) * HH;
    const int ho2 = (bg * 4 + 2) * HH;
    const int ho3 = (bg * 4 + 3) * HH;

    const int myb   = bg * 4 + bi;
    const int mycol = j0 + rh * 2 + ci;

    unsigned long long pk[16];
    auto initacc = [&]() {
#pragma unroll
        for (int g = 0; g < 4; g++) {
            unsigned long long b0 = (ks == 0) ? bp[g] : 0ULL;
            pk[g * 4 + 0] = b0;
            pk[g * 4 + 1] = b0;
            pk[g * 4 + 2] = b0;
            pk[g * 4 + 3] = b0;
        }
    };

    float myc = 0.0f, myh = 0.0f;

    // x projection for t=0 (h-independent; no barrier needed yet).
    initacc();
    mvphase<false>(pk, px0, px1, px2, px3, W4x, ks, subbase);

    for (int t = 0; t < TT; t++) {
        if (t) {
            const float* hb = g_hbuf[t & 1];
            mvphase<true>(pk, hb + ho0, hb + ho1, hb + ho2, hb + ho3,
                          W4h, ks, subbase);
        }

        // ---- Transposing 3-stage reduction over the 8-lane k-group ----
        // Stage A (xor 4): resolve column halves -> v[g][b] for own ci.
        float v[16];
#pragma unroll
        for (int i = 0; i < 16; i++) {
            float lo, hi;
            unpack2(pk[i], lo, hi);
            float mine = ci ? hi : lo;
            float send = ci ? lo : hi;
            v[i] = mine + __shfl_xor_sync(0xffffffffu, send, 4);
        }
        // Stage B (xor 1): resolve batch bit0 -> w2[g][j], j = b>>1.
        float w2[8];
#pragma unroll
        for (int g = 0; g < 4; g++) {
#pragma unroll
            for (int j = 0; j < 2; j++) {
                float a = v[g * 4 + j * 2 + 0];
                float b = v[g * 4 + j * 2 + 1];
                float mine = (bi & 1) ? b : a;
                float send = (bi & 1) ? a : b;
                w2[g * 2 + j] = mine + __shfl_xor_sync(0xffffffffu, send, 1);
            }
        }
        // Stage C (xor 2): resolve batch bit1 -> s[g] for own (ci,bi).
        float sg[4];
#pragma unroll
        for (int g = 0; g < 4; g++) {
            float a = w2[g * 2 + 0];
            float b = w2[g * 2 + 1];
            float mine = (bi >> 1) ? b : a;
            float send = (bi >> 1) ? a : b;
            sg[g] = mine + __shfl_xor_sync(0xffffffffu, send, 2);
        }

        // Pointwise (gate order: i, f, g, o).
        float gi = sig_fast(sg[0]);
        float gf = sig_fast(sg[1]);
        float gg = tanh_fast(sg[2]);
        float go = sig_fast(sg[3]);
        myc = fmaf(gf, myc, gi * gg);
        myh = go * tanh_fast(myc);

        out[((size_t)myb * TT + t) * HH + mycol] = myh;
        g_hbuf[(t + 1) & 1][myb * HH + mycol]    = myh;

        if (t == TT - 1) break;

        // Hoist x projection of t+1 before the barrier: independent work
        // that absorbs inter-CTA skew and barrier latency.
        initacc();
        px0 += II; px1 += II; px2 += II; px3 += II;
        mvphase<false>(pk, px0, px1, px2, px3, W4x, ks, subbase);

        __threadfence();   // publish this thread's h write before arrival
        __syncthreads();
        if (tid == 0) {
            unsigned a = atomicAdd(&g_count, 1u) + 1u;
            if (a % NCTA == 0u) {
                atomicAdd(&g_phase, 1u);
            } else {
                unsigned tgt = base + (unsigned)(t + 1);
                while ((int)(*(volatile unsigned*)&g_phase - tgt) < 0)
                    __nanosleep(64);
            }
            __threadfence();
        }
        __syncthreads();
    }

    const size_t TAIL = (size_t)BB * TT * HH;
    if (write_hn) out[TAIL + (size_t)myb * HH + mycol] = myh;
    if (write_cn) out[TAIL + (size_t)BB * HH + (size_t)myb * HH + mycol] = myc;
}

extern "C" void kernel_launch(void* const* d_in, const int* in_sizes, int n_in,
                              void* d_out, int out_size) {
    const float* x  = (const float*)d_in[0];
    const float* Wx = (const float*)d_in[1];
    const float* bx = (const float*)d_in[2];
    const float* Wh = (const float*)d_in[3];
    const float* bh = (const float*)d_in[4];

    const int SMEM_BYTES = 65536 + 128;
    cudaFuncSetAttribute(lstm_persistent,
                         cudaFuncAttributeMaxDynamicSharedMemorySize, SMEM_BYTES);
    cudaFuncSetAttribute(lstm_persistent,
                         cudaFuncAttributePreferredSharedMemoryCarveout, 100);

    const long long TAIL = (long long)BB * TT * HH;
    int whn = ((long long)out_size >= TAIL + (long long)BB * HH) ? 1 : 0;
    int wcn = ((long long)out_size >= TAIL + 2LL * BB * HH) ? 1 : 0;

    lstm_persistent<<<NCTA, NTHR, SMEM_BYTES>>>(x, Wx, bx, Wh, bh,
                                                (float*)d_out, whn, wcn);
}

// round 13
// speedup vs baseline: 1.2441x; 1.2110x over previous
#include <cuda_runtime.h>

// SimpleLSTM fused persistent kernel, v3.
// B=64, T=2048, I=H=512. 128 CTAs x 256 threads; CTA owns 4 hidden columns
// (16 gate rows). Weights staged in smem once (XOR-swizzled). h exchanged via
// global double buffer + one grid barrier per step.
// v3: early-arrive barrier (x-projection of t+1 runs between arrive and wait),
// distance-1 software-pipelined activation loads, sw==ks ALU trim.

#define BB 64
#define TT 2048
#define II 512
#define HH 512
#define NCTA 128
#define NTHR 256

__device__ __align__(16) float g_hbuf[2][BB * HH]; // [buf][b*HH + col]
__device__ unsigned g_count; // cumulative barrier arrivals (monotone)
__device__ unsigned g_phase; // cumulative barrier releases (monotone)

__device__ __forceinline__ float tanh_fast(float x) {
    float y;
    asm("tanh.approx.f32 %0, %1;" : "=f"(y) : "f"(x));
    return y;
}
__device__ __forceinline__ float sig_fast(float x) {
    return fmaf(0.5f, tanh_fast(0.5f * x), 0.5f);
}

__device__ __forceinline__ unsigned long long fma2(
    unsigned long long a, unsigned long long b, unsigned long long c) {
    unsigned long long d;
    asm("fma.rn.f32x2 %0, %1, %2, %3;" : "=l"(d) : "l"(a), "l"(b), "l"(c));
    return d;
}
__device__ __forceinline__ unsigned long long pack2(float lo, float hi) {
    unsigned long long r;
    asm("mov.b64 %0, {%1, %2};" : "=l"(r) : "f"(lo), "f"(hi));
    return r;
}
__device__ __forceinline__ unsigned long long dup2(float v) {
    unsigned long long r;
    asm("mov.b64 %0, {%1, %2};" : "=l"(r) : "f"(v), "f"(v));
    return r;
}
__device__ __forceinline__ void unpack2(unsigned long long p, float& lo, float& hi) {
    asm("mov.b64 {%0, %1}, %2;" : "=f"(lo), "=f"(hi) : "l"(p));
}

#define EL(v, e) ((e) == 0 ? (v).x : ((e) == 1 ? (v).y : ((e) == 2 ? (v).z : (v).w)))

// One K=512 matvec phase with distance-1 activation prefetch.
// pk[16] = packed (col0,col1) accumulators for gates 0..3 x batches 0..3.
// Weight smem: slot = k*4 + rh*2 + half at phys = slot ^ ks (since
// (k>>2)&7 == ks for every k this thread touches).
template <bool CG>
__device__ __forceinline__ void mvphase(
    unsigned long long* pk,
    const float* p0, const float* p1, const float* p2, const float* p3,
    const ulonglong2* __restrict__ W, int ks, int subbase)
{
    float4 c0, c1, c2, c3;
    {
        int k0 = ks * 4;
        if (CG) {
            c0 = __ldcg((const float4*)(p0 + k0));
            c1 = __ldcg((const float4*)(p1 + k0));
            c2 = __ldcg((const float4*)(p2 + k0));
            c3 = __ldcg((const float4*)(p3 + k0));
        } else {
            c0 = *(const float4*)(p0 + k0);
            c1 = *(const float4*)(p1 + k0);
            c2 = *(const float4*)(p2 + k0);
            c3 = *(const float4*)(p3 + k0);
        }
    }
#pragma unroll 4
    for (int q = 0; q < 16; q++) {
        float4 n0, n1, n2, n3;
        if (q < 15) {
            int kn = ((q + 1) * 8 + ks) * 4;
            if (CG) {
                n0 = __ldcg((const float4*)(p0 + kn));
                n1 = __ldcg((const float4*)(p1 + kn));
                n2 = __ldcg((const float4*)(p2 + kn));
                n3 = __ldcg((const float4*)(p3 + kn));
            } else {
                n0 = *(const float4*)(p0 + kn);
                n1 = *(const float4*)(p1 + kn);
                n2 = *(const float4*)(p2 + kn);
                n3 = *(const float4*)(p3 + kn);
            }
        }
        const int k0 = (q * 8 + ks) * 4;
#pragma unroll
        for (int e = 0; e < 4; e++) {
            int k = k0 + e;
            int sbase = k * 4 + subbase;
            ulonglong2 w0 = W[(sbase + 0) ^ ks]; // gates 0,1 (col-pairs)
            ulonglong2 w1 = W[(sbase + 1) ^ ks]; // gates 2,3
            unsigned long long d0 = dup2(EL(c0, e));
            unsigned long long d1 = dup2(EL(c1, e));
            unsigned long long d2 = dup2(EL(c2, e));
            unsigned long long d3 = dup2(EL(c3, e));
            pk[0]  = fma2(w0.x, d0, pk[0]);
            pk[1]  = fma2(w0.x, d1, pk[1]);
            pk[2]  = fma2(w0.x, d2, pk[2]);
            pk[3]  = fma2(w0.x, d3, pk[3]);
            pk[4]  = fma2(w0.y, d0, pk[4]);
            pk[5]  = fma2(w0.y, d1, pk[5]);
            pk[6]  = fma2(w0.y, d2, pk[6]);
            pk[7]  = fma2(w0.y, d3, pk[7]);
            pk[8]  = fma2(w1.x, d0, pk[8]);
            pk[9]  = fma2(w1.x, d1, pk[9]);
            pk[10] = fma2(w1.x, d2, pk[10]);
            pk[11] = fma2(w1.x, d3, pk[11]);
            pk[12] = fma2(w1.y, d0, pk[12]);
            pk[13] = fma2(w1.y, d1, pk[13]);
            pk[14] = fma2(w1.y, d2, pk[14]);
            pk[15] = fma2(w1.y, d3, pk[15]);
        }
        if (q < 15) { c0 = n0; c1 = n1; c2 = n2; c3 = n3; }
    }
}

__global__ void __launch_bounds__(NTHR, 1) lstm_persistent(
    const float* __restrict__ x,   // [B][T][I]
    const float* __restrict__ Wx,  // [4H][I]
    const float* __restrict__ bx,  // [4H]
    const float* __restrict__ Wh,  // [4H][H]
    const float* __restrict__ bh,  // [4H]
    float* __restrict__ out,       // [B][T][H] (+ optional h_n, c_n)
    int write_hn, int write_cn)
{
    extern __shared__ __align__(16) unsigned char smem_raw[];
    float4* W4x_st = (float4*)(smem_raw);
    float4* W4h_st = (float4*)(smem_raw + 32768);
    const ulonglong2* W4x = (const ulonglong2*)(smem_raw);
    const ulonglong2* W4h = (const ulonglong2*)(smem_raw + 32768);
    float* s_bias = (float*)(smem_raw + 65536);          // 16 floats
    unsigned* s_basep = (unsigned*)(smem_raw + 65536 + 64);

    const int tid  = threadIdx.x;
    const int warp = tid >> 5;
    const int lane = tid & 31;
    const int rh   = lane >> 4;        // column-pair half (rows rh*8..rh*8+7)
    const int bgl  = (lane >> 3) & 1;
    const int ks   = lane & 7;         // k-split lane
    const int bg   = warp * 2 + bgl;   // batch group: batches bg*4..+3
    const int ci   = ks >> 2;          // this lane's column within pair
    const int bi   = ks & 3;           // this lane's batch within group
    const int j0   = blockIdx.x * 4;
    const int subbase = rh * 2;

    // ---- Stage weight slices (16 rows x 512 k, both matrices) ----
    for (int idx = tid; idx < 2048; idx += NTHR) {
        int k = idx >> 2, sub = idx & 3;
        int rrh = sub >> 1, half = sub & 1;
        int sw = (k >> 2) & 7;
        int phys = idx ^ sw;
        int colb = j0 + rrh * 2;
#define GR(m) ((size_t)(half * 2 + ((m) >> 1)) * HH + colb + ((m) & 1))
        float4 vx, vh;
        vx.x = Wx[GR(0) * II + k];
        vx.y = Wx[GR(1) * II + k];
        vx.z = Wx[GR(2) * II + k];
        vx.w = Wx[GR(3) * II + k];
        vh.x = Wh[GR(0) * HH + k];
        vh.y = Wh[GR(1) * HH + k];
        vh.z = Wh[GR(2) * HH + k];
        vh.w = Wh[GR(3) * HH + k];
#undef GR
        W4x_st[phys] = vx;
        W4h_st[phys] = vh;
    }
    if (tid < 16) {
        int rrh = tid >> 3, g = (tid >> 1) & 3, cc = tid & 1;
        size_t row = (size_t)g * HH + j0 + rrh * 2 + cc;
        s_bias[tid] = bx[row] + bh[row];
    }
    if (tid == 0) *s_basep = *(volatile unsigned*)&g_phase;
    __syncthreads();

    const unsigned base = *s_basep;

    unsigned long long bp[4];
#pragma unroll
    for (int g = 0; g < 4; g++)
        bp[g] = pack2(s_bias[rh * 8 + g * 2 + 0], s_bias[rh * 8 + g * 2 + 1]);

    const float* px0 = x + (size_t)(bg * 4 + 0) * TT * II;
    const float* px1 = x + (size_t)(bg * 4 + 1) * TT * II;
    const float* px2 = x + (size_t)(bg * 4 + 2) * TT * II;
    const float* px3 = x + (size_t)(bg * 4 + 3) * TT * II;
    const int ho0 = (bg * 4 + 0) * HH;
    const int ho1 = (bg * 4 + 1) * HH;
    const int ho2 = (bg * 4 + 2) * HH;
    const int ho3 = (bg * 4 + 3) * HH;

    const int myb   = bg * 4 + bi;
    const int mycol = j0 + rh * 2 + ci;

    unsigned long long pk[16];
    auto initacc = [&]() {
#pragma unroll
        for (int g = 0; g < 4; g++) {
            unsigned long long b0 = (ks == 0) ? bp[g] : 0ULL;
            pk[g * 4 + 0] = b0;
            pk[g * 4 + 1] = b0;
            pk[g * 4 + 2] = b0;
            pk[g * 4 + 3] = b0;
        }
    };

    float myc = 0.0f, myh = 0.0f;

    // x projection for t=0 (h-independent; no barrier needed yet).
    initacc();
    mvphase<false>(pk, px0, px1, px2, px3, W4x, ks, subbase);

    for (int t = 0; t < TT; t++) {
        if (t) {
            const float* hb = g_hbuf[t & 1];
            mvphase<true>(pk, hb + ho0, hb + ho1, hb + ho2, hb + ho3,
                          W4h, ks, subbase);
        }

        // ---- Transposing 3-stage reduction over the 8-lane k-group ----
        float v[16];
#pragma unroll
        for (int i = 0; i < 16; i++) {
            float lo, hi;
            unpack2(pk[i], lo, hi);
            float mine = ci ? hi : lo;
            float send = ci ? lo : hi;
            v[i] = mine + __shfl_xor_sync(0xffffffffu, send, 4);
        }
        float w2[8];
#pragma unroll
        for (int g = 0; g < 4; g++) {
#pragma unroll
            for (int j = 0; j < 2; j++) {
                float a = v[g * 4 + j * 2 + 0];
                float b = v[g * 4 + j * 2 + 1];
                float mine = (bi & 1) ? b : a;
                float send = (bi & 1) ? a : b;
                w2[g * 2 + j] = mine + __shfl_xor_sync(0xffffffffu, send, 1);
            }
        }
        float sg[4];
#pragma unroll
        for (int g = 0; g < 4; g++) {
            float a = w2[g * 2 + 0];
            float b = w2[g * 2 + 1];
            float mine = (bi >> 1) ? b : a;
            float send = (bi >> 1) ? a : b;
            sg[g] = mine + __shfl_xor_sync(0xffffffffu, send, 2);
        }

        // Pointwise (gate order: i, f, g, o).
        float gi = sig_fast(sg[0]);
        float gf = sig_fast(sg[1]);
        float gg = tanh_fast(sg[2]);
        float go = sig_fast(sg[3]);
        myc = fmaf(gf, myc, gi * gg);
        myh = go * tanh_fast(myc);

        out[((size_t)myb * TT + t) * HH + mycol] = myh;
        __stcg(&g_hbuf[(t + 1) & 1][myb * HH + mycol], myh);

        if (t == TT - 1) break;

        // ---- Early arrive: publish h, arrive, THEN compute x-phase of t+1,
        // THEN wait. The x-phase hides barrier release latency + CTA skew. ----
        __threadfence();   // publish this thread's h store
        __syncthreads();   // all stores in CTA done
        if (tid == 0) {
            unsigned a = atomicAdd(&g_count, 1u) + 1u;
            if (a % NCTA == 0u) atomicAdd(&g_phase, 1u);
        }

        initacc();
        px0 += II; px1 += II; px2 += II; px3 += II;
        mvphase<false>(pk, px0, px1, px2, px3, W4x, ks, subbase);

        if (tid == 0) {
            unsigned tgt = base + (unsigned)(t + 1);
            while ((int)(*(volatile unsigned*)&g_phase - tgt) < 0)
                __nanosleep(32);
            __threadfence();
        }
        __syncthreads();
    }

    const size_t TAIL = (size_t)BB * TT * HH;
    if (write_hn) out[TAIL + (size_t)myb * HH + mycol] = myh;
    if (write_cn) out[TAIL + (size_t)BB * HH + (size_t)myb * HH + mycol] = myc;
}

extern "C" void kernel_launch(void* const* d_in, const int* in_sizes, int n_in,
                              void* d_out, int out_size) {
    const float* x  = (const float*)d_in[0];
    const float* Wx = (const float*)d_in[1];
    const float* bx = (const float*)d_in[2];
    const float* Wh = (const float*)d_in[3];
    const float* bh = (const float*)d_in[4];

    const int SMEM_BYTES = 65536 + 128;
    cudaFuncSetAttribute(lstm_persistent,
                         cudaFuncAttributeMaxDynamicSharedMemorySize, SMEM_BYTES);
    cudaFuncSetAttribute(lstm_persistent,
                         cudaFuncAttributePreferredSharedMemoryCarveout, 100);

    const long long TAIL = (long long)BB * TT * HH;
    int whn = ((long long)out_size >= TAIL + (long long)BB * HH) ? 1 : 0;
    int wcn = ((long long)out_size >= TAIL + 2LL * BB * HH) ? 1 : 0;

    lstm_persistent<<<NCTA, NTHR, SMEM_BYTES>>>(x, Wx, bx, Wh, bh,
                                                (float*)d_out, whn, wcn);
}

// round 14
// speedup vs baseline: 1.2808x; 1.0295x over previous
#include <cuda_runtime.h>

// SimpleLSTM fused persistent kernel, v4.
// B=64, T=2048, I=H=512. 128 CTAs x 256 threads; CTA owns 4 hidden columns
// (16 gate rows). Weights staged in smem once (XOR-swizzled). h exchanged via
// global double buffer + flag-array grid barrier per step.
// v4: f32x2 packing over k-parity (weight AND activation operands are native
// register-pair halves of 128-bit loads -> no packing MOVs), flag-array
// barrier (no same-address atomic serialization), early-arrive retained.

#define BB 64
#define TT 2048
#define II 512
#define HH 512
#define NCTA 128
#define NTHR 256

__device__ __align__(16) float g_hbuf[2][BB * HH]; // [buf][b*HH + col]
__device__ unsigned g_flags[NCTA];                 // monotone per-CTA epochs

__device__ __forceinline__ float tanh_fast(float x) {
    float y;
    asm("tanh.approx.f32 %0, %1;" : "=f"(y) : "f"(x));
    return y;
}
__device__ __forceinline__ float sig_fast(float x) {
    return fmaf(0.5f, tanh_fast(0.5f * x), 0.5f);
}

__device__ __forceinline__ unsigned long long fma2(
    unsigned long long a, unsigned long long b, unsigned long long c) {
    unsigned long long d;
    asm("fma.rn.f32x2 %0, %1, %2, %3;" : "=l"(d) : "l"(a), "l"(b), "l"(c));
    return d;
}
__device__ __forceinline__ unsigned long long pack2(float lo, float hi) {
    unsigned long long r;
    asm("mov.b64 %0, {%1, %2};" : "=l"(r) : "f"(lo), "f"(hi));
    return r;
}
__device__ __forceinline__ void unpack2(unsigned long long p, float& lo, float& hi) {
    asm("mov.b64 {%0, %1}, %2;" : "=f"(lo), "=f"(hi) : "l"(p));
}

// One K=512 matvec phase, packed over k-parity.
// pk[32]: index (g*2 + c2)*4 + b; each holds (sum over even k, sum over odd k).
// Weight smem (per matrix): float4 slot (kp, rp), rp = g*2 + ch, content
//   ( W[g][col 2ch  ][2kp], W[g][col 2ch  ][2kp+1],
//     W[g][col 2ch+1][2kp], W[g][col 2ch+1][2kp+1] )
// stored at phys = kp*8 + (rp ^ ((kp>>1)&7)).
// This thread touches kp = 16q + 2ks + p, so (kp>>1)&7 == ks (uniform).
// Per instruction (g,p): 16 lanes (rh,ks) hit 8 distinct 16B offsets
// within a 128B block (offset = (g*2+rh)^ks), each twice (broadcast):
// conflict-free LDS.128.
template <bool CG>
__device__ __forceinline__ void mvphase(
    unsigned long long* pk,
    const float* p0, const float* p1, const float* p2, const float* p3,
    const float4* __restrict__ W, int ks, int rh)
{
    const int tb = 16 * ks; // float4-slot base offset for q=0, p=0
    const int o0 = (0 + rh) ^ ks; // g=0: (g*2+rh)^ks
    const int o1 = (2 + rh) ^ ks;
    const int o2 = (4 + rh) ^ ks;
    const int o3 = (6 + rh) ^ ks;

    float4 c0, c1, c2, c3;
    {
        const int k0 = ks * 4;
        if (CG) {
            c0 = __ldcg((const float4*)(p0 + k0));
            c1 = __ldcg((const float4*)(p1 + k0));
            c2 = __ldcg((const float4*)(p2 + k0));
            c3 = __ldcg((const float4*)(p3 + k0));
        } else {
            c0 = *(const float4*)(p0 + k0);
            c1 = *(const float4*)(p1 + k0);
            c2 = *(const float4*)(p2 + k0);
            c3 = *(const float4*)(p3 + k0);
        }
    }
#pragma unroll 4
    for (int q = 0; q < 16; q++) {
        float4 n0, n1, n2, n3;
        if (q < 15) {
            const int kn = ((q + 1) * 8 + ks) * 4;
            if (CG) {
                n0 = __ldcg((const float4*)(p0 + kn));
                n1 = __ldcg((const float4*)(p1 + kn));
                n2 = __ldcg((const float4*)(p2 + kn));
                n3 = __ldcg((const float4*)(p3 + kn));
            } else {
                n0 = *(const float4*)(p0 + kn);
                n1 = *(const float4*)(p1 + kn);
                n2 = *(const float4*)(p2 + kn);
                n3 = *(const float4*)(p3 + kn);
            }
        }
        const int qb = 128 * q + tb;
        // activation k-pairs: native halves of the float4 registers
        const unsigned long long aL0 = pack2(c0.x, c0.y), aH0 = pack2(c0.z, c0.w);
        const unsigned long long aL1 = pack2(c1.x, c1.y), aH1 = pack2(c1.z, c1.w);
        const unsigned long long aL2 = pack2(c2.x, c2.y), aH2 = pack2(c2.z, c2.w);
        const unsigned long long aL3 = pack2(c3.x, c3.y), aH3 = pack2(c3.z, c3.w);
#pragma unroll
        for (int g = 0; g < 4; g++) {
            const int off = (g == 0) ? o0 : (g == 1) ? o1 : (g == 2) ? o2 : o3;
            // p = 0 (k-pair 2kp with kp = 16q+2ks)
            {
                float4 w4 = W[qb + off];
                unsigned long long wA = pack2(w4.x, w4.y); // col 2rh
                unsigned long long wB = pack2(w4.z, w4.w); // col 2rh+1
                unsigned long long* a0 = &pk[(g * 2 + 0) * 4];
                unsigned long long* a1 = &pk[(g * 2 + 1) * 4];
                a0[0] = fma2(wA, aL0, a0[0]);
                a0[1] = fma2(wA, aL1, a0[1]);
                a0[2] = fma2(wA, aL2, a0[2]);
                a0[3] = fma2(wA, aL3, a0[3]);
                a1[0] = fma2(wB, aL0, a1[0]);
                a1[1] = fma2(wB, aL1, a1[1]);
                a1[2] = fma2(wB, aL2, a1[2]);
                a1[3] = fma2(wB, aL3, a1[3]);
            }
            // p = 1
            {
                float4 w4 = W[qb + 8 + off];
                unsigned long long wA = pack2(w4.x, w4.y);
                unsigned long long wB = pack2(w4.z, w4.w);
                unsigned long long* a0 = &pk[(g * 2 + 0) * 4];
                unsigned long long* a1 = &pk[(g * 2 + 1) * 4];
                a0[0] = fma2(wA, aH0, a0[0]);
                a0[1] = fma2(wA, aH1, a0[1]);
                a0[2] = fma2(wA, aH2, a0[2]);
                a0[3] = fma2(wA, aH3, a0[3]);
                a1[0] = fma2(wB, aH0, a1[0]);
                a1[1] = fma2(wB, aH1, a1[1]);
                a1[2] = fma2(wB, aH2, a1[2]);
                a1[3] = fma2(wB, aH3, a1[3]);
            }
        }
        if (q < 15) { c0 = n0; c1 = n1; c2 = n2; c3 = n3; }
    }
}

__global__ void __launch_bounds__(NTHR, 1) lstm_persistent(
    const float* __restrict__ x,   // [B][T][I]
    const float* __restrict__ Wx,  // [4H][I]
    const float* __restrict__ bx,  // [4H]
    const float* __restrict__ Wh,  // [4H][H]
    const float* __restrict__ bh,  // [4H]
    float* __restrict__ out,       // [B][T][H] (+ optional h_n, c_n)
    int write_hn, int write_cn)
{
    extern __shared__ __align__(16) unsigned char smem_raw[];
    float4* W4x = (float4*)(smem_raw);
    float4* W4h = (float4*)(smem_raw + 32768);
    float*  s_bias = (float*)(smem_raw + 65536); // 16 floats

    const int tid  = threadIdx.x;
    const int warp = tid >> 5;
    const int lane = tid & 31;
    const int rh   = lane >> 4;        // column-pair half: cols (2rh, 2rh+1)
    const int bgl  = (lane >> 3) & 1;
    const int ks   = lane & 7;         // k-split lane
    const int bg   = warp * 2 + bgl;   // batches bg*4..bg*4+3
    const int ci   = ks >> 2;          // this lane's column within pair
    const int bi   = ks & 3;           // this lane's batch within group
    const int j0   = blockIdx.x * 4;

    // ---- Stage weight slices (float4 slot (kp, rp), swizzled) ----
    for (int idx = tid; idx < 2048; idx += NTHR) {
        const int kp = idx >> 3, rp = idx & 7;
        const int g = rp >> 1, ch = rp & 1;
        const int phys = kp * 8 + (rp ^ ((kp >> 1) & 7));
        const size_t rA = (size_t)g * HH + j0 + ch * 2;     // col 2ch
        const size_t rB = rA + 1;                           // col 2ch+1
        const int k0 = kp * 2;
        float4 vx, vh;
        vx.x = Wx[rA * II + k0];
        vx.y = Wx[rA * II + k0 + 1];
        vx.z = Wx[rB * II + k0];
        vx.w = Wx[rB * II + k0 + 1];
        vh.x = Wh[rA * HH + k0];
        vh.y = Wh[rA * HH + k0 + 1];
        vh.z = Wh[rB * HH + k0];
        vh.w = Wh[rB * HH + k0 + 1];
        W4x[phys] = vx;
        W4h[phys] = vh;
    }
    if (tid < 16) {
        const int g = tid >> 2, c = tid & 3;
        const size_t row = (size_t)g * HH + j0 + c;
        s_bias[g * 4 + c] = bx[row] + bh[row];
    }
    __syncthreads();

    const unsigned base = __ldcg(&g_flags[blockIdx.x]); // equal across CTAs

    unsigned long long bp[8]; // [g*2 + c2] = (bias, 0)
#pragma unroll
    for (int g = 0; g < 4; g++) {
        bp[g * 2 + 0] = pack2(s_bias[g * 4 + 2 * rh + 0], 0.0f);
        bp[g * 2 + 1] = pack2(s_bias[g * 4 + 2 * rh + 1], 0.0f);
    }

    const float* px0 = x + (size_t)(bg * 4 + 0) * TT * II;
    const float* px1 = x + (size_t)(bg * 4 + 1) * TT * II;
    const float* px2 = x + (size_t)(bg * 4 + 2) * TT * II;
    const float* px3 = x + (size_t)(bg * 4 + 3) * TT * II;
    const int ho0 = (bg * 4 + 0) * HH;
    const int ho1 = (bg * 4 + 1) * HH;
    const int ho2 = (bg * 4 + 2) * HH;
    const int ho3 = (bg * 4 + 3) * HH;

    const int myb   = bg * 4 + bi;
    const int mycol = j0 + rh * 2 + ci;

    unsigned long long pk[32];
    auto initacc = [&]() {
#pragma unroll
        for (int gc = 0; gc < 8; gc++) {
            const unsigned long long b0 = (ks == 0) ? bp[gc] : 0ULL;
            pk[gc * 4 + 0] = b0;
            pk[gc * 4 + 1] = b0;
            pk[gc * 4 + 2] = b0;
            pk[gc * 4 + 3] = b0;
        }
    };

    float myc = 0.0f, myh = 0.0f;

    // x projection for t=0 (h-independent; no barrier needed yet).
    initacc();
    mvphase<false>(pk, px0, px1, px2, px3, W4x, ks, rh);

    for (int t = 0; t < TT; t++) {
        if (t) {
            const float* hb = g_hbuf[t & 1];
            mvphase<true>(pk, hb + ho0, hb + ho1, hb + ho2, hb + ho3,
                          W4h, ks, rh);
        }

        // ---- Fold k-parity, then transposing 3-stage shfl reduction ----
        float s[32]; // (g*2 + c2)*4 + b
#pragma unroll
        for (int i = 0; i < 32; i++) {
            float lo, hi;
            unpack2(pk[i], lo, hi);
            s[i] = lo + hi;
        }
        // Stage A (xor 4): resolve column within pair -> v[g][b].
        float v[16];
#pragma unroll
        for (int g = 0; g < 4; g++) {
#pragma unroll
            for (int b = 0; b < 4; b++) {
                const float mine = ci ? s[(g * 2 + 1) * 4 + b] : s[(g * 2 + 0) * 4 + b];
                const float send = ci ? s[(g * 2 + 0) * 4 + b] : s[(g * 2 + 1) * 4 + b];
                v[g * 4 + b] = mine + __shfl_xor_sync(0xffffffffu, send, 4);
            }
        }
        // Stage B (xor 1): resolve batch bit0 -> w2[g][j], j = b>>1.
        float w2[8];
#pragma unroll
        for (int g = 0; g < 4; g++) {
#pragma unroll
            for (int j = 0; j < 2; j++) {
                const float a = v[g * 4 + j * 2 + 0];
                const float b = v[g * 4 + j * 2 + 1];
                const float mine = (bi & 1) ? b : a;
                const float send = (bi & 1) ? a : b;
                w2[g * 2 + j] = mine + __shfl_xor_sync(0xffffffffu, send, 1);
            }
        }
        // Stage C (xor 2): resolve batch bit1 -> sg[g].
        float sg[4];
#pragma unroll
        for (int g = 0; g < 4; g++) {
            const float a = w2[g * 2 + 0];
            const float b = w2[g * 2 + 1];
            const float mine = (bi >> 1) ? b : a;
            const float send = (bi >> 1) ? a : b;
            sg[g] = mine + __shfl_xor_sync(0xffffffffu, send, 2);
        }

        // Pointwise (gate order: i, f, g, o).
        const float gi = sig_fast(sg[0]);
        const float gf = sig_fast(sg[1]);
        const float gg = tanh_fast(sg[2]);
        const float go = sig_fast(sg[3]);
        myc = fmaf(gf, myc, gi * gg);
        myh = go * tanh_fast(myc);

        out[((size_t)myb * TT + t) * HH + mycol] = myh;
        __stcg(&g_hbuf[(t + 1) & 1][myb * HH + mycol], myh);

        if (t == TT - 1) break;

        // ---- Early arrive (flag array), x-phase of t+1, then wait. ----
        __threadfence();   // publish my h store (gpu scope)
        __syncthreads();   // all threads' fences done
        const unsigned tgt = base + (unsigned)(t + 1);
        if (tid == 0) __stcg(&g_flags[blockIdx.x], tgt);

        initacc();
        px0 += II; px1 += II; px2 += II; px3 += II;
        mvphase<false>(pk, px0, px1, px2, px3, W4x, ks, rh);

        int ok;
        do {
            ok = 1;
            if (tid < NCTA)
                ok = ((int)(__ldcg(&g_flags[tid]) - tgt) >= 0);
        } while (!__syncthreads_and(ok));
        __threadfence(); // acquire: order subsequent h loads after flag reads
    }

    const size_t TAIL = (size_t)BB * TT * HH;
    if (write_hn) out[TAIL + (size_t)myb * HH + mycol] = myh;
    if (write_cn) out[TAIL + (size_t)BB * HH + (size_t)myb * HH + mycol] = myc;
}

extern "C" void kernel_launch(void* const* d_in, const int* in_sizes, int n_in,
                              void* d_out, int out_size) {
    const float* x  = (const float*)d_in[0];
    const float* Wx = (const float*)d_in[1];
    const float* bx = (const float*)d_in[2];
    const float* Wh = (const float*)d_in[3];
    const float* bh = (const float*)d_in[4];

    const int SMEM_BYTES = 65536 + 128;
    cudaFuncSetAttribute(lstm_persistent,
                         cudaFuncAttributeMaxDynamicSharedMemorySize, SMEM_BYTES);
    cudaFuncSetAttribute(lstm_persistent,
                         cudaFuncAttributePreferredSharedMemoryCarveout, 100);

    const long long TAIL = (long long)BB * TT * HH;
    int whn = ((long long)out_size >= TAIL + (long long)BB * HH) ? 1 : 0;
    int wcn = ((long long)out_size >= TAIL + 2LL * BB * HH) ? 1 : 0;

    lstm_persistent<<<NCTA, NTHR, SMEM_BYTES>>>(x, Wx, bx, Wh, bh,
                                                (float*)d_out, whn, wcn);
}